// round 12
// baseline (speedup 1.0000x reference)
#include <cuda_runtime.h>
#include <cuda_bf16.h>
#include <cstdint>

#define Bsz 65536
#define Hd 512
#define Dd 64
typedef __nv_bfloat16 bf;

// ---- static device scratch (no cudaMalloc allowed) ----
static __device__ __align__(16) bf g_Wz_h[3][Hd * Hd],  g_Wz_l[3][Hd * Hd];   // fwd [n][k]
static __device__ __align__(16) bf g_WzT_h[3][Hd * Hd], g_WzT_l[3][Hd * Hd];  // bwd [n][k]
static __device__ __align__(16) bf g_Wz0_h[Hd * Dd],    g_Wz0_l[Hd * Dd];
static __device__ __align__(16) bf g_Wx_h[3][Hd * Dd],  g_Wx_l[3][Hd * Dd];
static __device__ __align__(16) bf g_GT_h[4][Dd * Hd],  g_GT_l[4][Dd * Hd];   // grad B [64][512]
static __device__ __align__(16) bf g_x_h[(size_t)Bsz * Dd],  g_x_l[(size_t)Bsz * Dd];
static __device__ __align__(16) bf g_z_h[3][(size_t)Bsz * Hd], g_z_l[3][(size_t)Bsz * Hd];
static __device__ __align__(16) bf g_d4_h[(size_t)Bsz * Hd], g_d4_l[(size_t)Bsz * Hd];
static __device__ float g_gpart[4][(size_t)Bsz * Dd];   // grad partials per segment

struct PassArgs {
    const bf *Ah[4], *Al[4], *Bh[4], *Bl[4];
    int K[4]; int nseg; int mode;       // 0 fwd, 1 last, 2 bwd, 3 grad
    const float *bias, *aux;
    const bf *sh, *sl;                  // z planes for sigmoid recompute (mode 2)
    bf *oh, *ol;                        // bf16 hi/lo output planes
};
static __device__ PassArgs g_pass[8];

// ---- PTX helpers ----
__device__ __forceinline__ uint32_t smem_u32(const void* p) {
    uint32_t a;
    asm("{ .reg .u64 t; cvta.to.shared.u64 t, %1; cvt.u32.u64 %0, t; }" : "=r"(a) : "l"(p));
    return a;
}
__device__ __forceinline__ void cpa16(uint32_t dst, const void* src) {
    asm volatile("cp.async.cg.shared.global [%0], [%1], 16;" :: "r"(dst), "l"(src));
}
#define CP_COMMIT() asm volatile("cp.async.commit_group;" ::: "memory")
#define CP_WAIT1()  asm volatile("cp.async.wait_group 1;" ::: "memory")
#define CP_WAIT0()  asm volatile("cp.async.wait_group 0;" ::: "memory")
#define LDSM4(R, addr) \
    asm volatile("ldmatrix.sync.aligned.m8n8.x4.shared.b16 {%0,%1,%2,%3}, [%4];" \
        : "=r"((R)[0]), "=r"((R)[1]), "=r"((R)[2]), "=r"((R)[3]) : "r"(addr))
#define MMA16816(c, A, b0, b1) \
    asm volatile("mma.sync.aligned.m16n8k16.row.col.f32.bf16.bf16.f32 " \
        "{%0,%1,%2,%3}, {%4,%5,%6,%7}, {%8,%9}, {%0,%1,%2,%3};" \
        : "+f"((c)[0]), "+f"((c)[1]), "+f"((c)[2]), "+f"((c)[3]) \
        : "r"((A)[0]), "r"((A)[1]), "r"((A)[2]), "r"((A)[3]), "r"(b0), "r"(b1))

__device__ __forceinline__ void act(float p, float& z, float& s) {
    float e = __expf(-fabsf(p));
    float r = 1.0f / (1.0f + e);
    z = fmaxf(p, 0.0f) + log1pf(e);
    s = (p >= 0.0f) ? r : e * r;
}
__device__ __forceinline__ void bsplit(float v, bf& h, bf& l) {
    h = __float2bfloat16(v);
    l = __float2bfloat16(v - __bfloat162float(h));
}
__device__ __forceinline__ uint32_t pk2(bf a, bf b) {
    __nv_bfloat162 t(a, b);
    return *reinterpret_cast<uint32_t*>(&t);
}
__device__ __forceinline__ void st_split(bf* ph, bf* pl, size_t off, float v0, float v1) {
    bf h0, l0, h1, l1;
    bsplit(v0, h0, l0); bsplit(v1, h1, l1);
    *reinterpret_cast<uint32_t*>(ph + off) = pk2(h0, h1);
    *reinterpret_cast<uint32_t*>(pl + off) = pk2(l0, l1);
}
__device__ __forceinline__ uint32_t swz(int r, int jb) {
    return (uint32_t)((r << 6) + ((jb ^ ((r >> 1) & 3)) << 4));
}

// ---- prep 1: coalesced splits (fwd planes, x) + pass args ----
__global__ void prep_all(const float* __restrict__ Wz0, const float* __restrict__ Wz1,
                         const float* __restrict__ Wz2, const float* __restrict__ Wz3,
                         const float* __restrict__ Wx0, const float* __restrict__ Wx1,
                         const float* __restrict__ Wx2, const float* __restrict__ state,
                         const float* bz0, const float* bx0, const float* bx1,
                         const float* bx2, const float* WzL, const float* WxL)
{
    const float* Wz[3] = { Wz1, Wz2, Wz3 };
    const float* Wx[3] = { Wx0, Wx1, Wx2 };
    for (int i = blockIdx.x * blockDim.x + threadIdx.x; i < Hd * Hd;
         i += gridDim.x * blockDim.x) {
        #pragma unroll
        for (int l = 0; l < 3; l++) {
            bf h, lo; bsplit(Wz[l][i], h, lo);
            g_Wz_h[l][i] = h; g_Wz_l[l][i] = lo;
        }
        if (i < Hd * Dd) {
            bf h, lo; bsplit(Wz0[i], h, lo);
            g_Wz0_h[i] = h; g_Wz0_l[i] = lo;
            #pragma unroll
            for (int l = 0; l < 3; l++) {
                bsplit(Wx[l][i], h, lo);
                g_Wx_h[l][i] = h; g_Wx_l[l][i] = lo;
            }
        }
    }
    for (size_t i = blockIdx.x * blockDim.x + threadIdx.x; i < (size_t)Bsz * Dd;
         i += (size_t)gridDim.x * blockDim.x) {
        bf h, l; bsplit(state[i] - 1.0f, h, l);
        g_x_h[i] = h; g_x_l[i] = l;
    }
    if (blockIdx.x == 0 && threadIdx.x == 0) {
        auto set = [] (int p, int nseg, int mode, const float* bias, const float* aux,
                       const bf* sh, const bf* sl, bf* oh, bf* ol) {
            PassArgs& a = g_pass[p];
            a.nseg = nseg; a.mode = mode; a.bias = bias; a.aux = aux;
            a.sh = sh; a.sl = sl; a.oh = oh; a.ol = ol;
        };
        auto seg = [] (int p, int s, const bf* Ah, const bf* Al, const bf* Bh, const bf* Bl, int K) {
            PassArgs& a = g_pass[p];
            a.Ah[s] = Ah; a.Al[s] = Al; a.Bh[s] = Bh; a.Bl[s] = Bl; a.K[s] = K;
        };
        set(0, 1, 0, bz0, 0, 0, 0, g_z_h[0], g_z_l[0]);
        seg(0, 0, g_x_h, g_x_l, g_Wz0_h, g_Wz0_l, Dd);
        set(1, 2, 0, bx0, 0, 0, 0, g_z_h[1], g_z_l[1]);
        seg(1, 0, g_z_h[0], g_z_l[0], g_Wz_h[0], g_Wz_l[0], Hd);
        seg(1, 1, g_x_h, g_x_l, g_Wx_h[0], g_Wx_l[0], Dd);
        set(2, 2, 0, bx1, 0, 0, 0, g_z_h[2], g_z_l[2]);
        seg(2, 0, g_z_h[1], g_z_l[1], g_Wz_h[1], g_Wz_l[1], Hd);
        seg(2, 1, g_x_h, g_x_l, g_Wx_h[1], g_Wx_l[1], Dd);
        set(3, 2, 1, bx2, WzL, 0, 0, g_d4_h, g_d4_l);
        seg(3, 0, g_z_h[2], g_z_l[2], g_Wz_h[2], g_Wz_l[2], Hd);
        seg(3, 1, g_x_h, g_x_l, g_Wx_h[2], g_Wx_l[2], Dd);
        set(4, 1, 2, 0, 0, g_z_h[2], g_z_l[2], g_z_h[2], g_z_l[2]);
        seg(4, 0, g_d4_h, g_d4_l, g_WzT_h[2], g_WzT_l[2], Hd);
        set(5, 1, 2, 0, 0, g_z_h[1], g_z_l[1], g_z_h[1], g_z_l[1]);
        seg(5, 0, g_z_h[2], g_z_l[2], g_WzT_h[1], g_WzT_l[1], Hd);
        set(6, 1, 2, 0, 0, g_z_h[0], g_z_l[0], g_z_h[0], g_z_l[0]);
        seg(6, 0, g_z_h[1], g_z_l[1], g_WzT_h[0], g_WzT_l[0], Hd);
        set(7, 4, 3, 0, WxL, 0, 0, 0, 0);
        seg(7, 0, g_z_h[0], g_z_l[0], g_GT_h[0], g_GT_l[0], Hd);
        seg(7, 1, g_z_h[1], g_z_l[1], g_GT_h[1], g_GT_l[1], Hd);
        seg(7, 2, g_z_h[2], g_z_l[2], g_GT_h[2], g_GT_l[2], Hd);
        seg(7, 3, g_d4_h, g_d4_l, g_GT_h[3], g_GT_l[3], Hd);
    }
}

// ---- prep 2: coalesced 32x32 smem-tile transposes ----
__global__ void prep_trans(const float* __restrict__ Wz0, const float* __restrict__ Wz1,
                           const float* __restrict__ Wz2, const float* __restrict__ Wz3,
                           const float* __restrict__ Wx0, const float* __restrict__ Wx1,
                           const float* __restrict__ Wx2)
{
    __shared__ float tile[32][33];
    const int tid = threadIdx.x;
    const int c = tid & 31, r0 = tid >> 5;
    const int b = blockIdx.x;

    if (b < 256) {
        const float* src[3] = { Wz1, Wz2, Wz3 };
        bf* dh[3] = { g_WzT_h[0], g_WzT_h[1], g_WzT_h[2] };
        bf* dl[3] = { g_WzT_l[0], g_WzT_l[1], g_WzT_l[2] };
        const int tr = (b >> 4) * 32, tc = (b & 15) * 32;
        for (int l = 0; l < 3; l++) {
            __syncthreads();
            #pragma unroll
            for (int it = 0; it < 4; it++) {
                int r = r0 + it * 8;
                tile[r][c] = src[l][(tr + r) * Hd + tc + c];
            }
            __syncthreads();
            #pragma unroll
            for (int it = 0; it < 4; it++) {
                int r = r0 + it * 8;
                bf h, lo; bsplit(tile[c][r], h, lo);
                dh[l][(tc + r) * Hd + tr + c] = h;
                dl[l][(tc + r) * Hd + tr + c] = lo;
            }
        }
    } else {
        const float* src[4] = { Wz0, Wx0, Wx1, Wx2 };
        const int idx = b - 256;
        const int tr = (idx >> 1) * 32, tc = (idx & 1) * 32;
        for (int l = 0; l < 4; l++) {
            __syncthreads();
            #pragma unroll
            for (int it = 0; it < 4; it++) {
                int r = r0 + it * 8;
                tile[r][c] = src[l][(tr + r) * Dd + tc + c];
            }
            __syncthreads();
            #pragma unroll
            for (int it = 0; it < 4; it++) {
                int r = r0 + it * 8;
                bf h, lo; bsplit(tile[c][r], h, lo);
                g_GT_h[l][(tc + r) * Hd + tr + c] = h;
                g_GT_l[l][(tc + r) * Hd + tr + c] = lo;
            }
        }
    }
}

__global__ void grad_reduce(const float* __restrict__ WxL, float* __restrict__ out)
{
    for (size_t i = blockIdx.x * blockDim.x + threadIdx.x; i < (size_t)Bsz * Dd;
         i += (size_t)gridDim.x * blockDim.x) {
        out[i] = g_gpart[0][i] + g_gpart[1][i] + g_gpart[2][i] + g_gpart[3][i]
               + __ldg(WxL + (i & 63));
    }
}

// ---------------------------------------------------------------------------
// GEMM pass: CTA 128m x 64n, 256 thr, bf16 3-product mma.sync,
// 3-stage cp.async pipeline, 3 CTAs/SM (R9 structure).
// ---------------------------------------------------------------------------
#define NT 64
#define NW8 4
#define APL 8192            // A plane bytes (128 x 32 x bf16)
#define BPL 4096            // B plane bytes (64 x 32 x bf16)
#define STG (16384 + 2 * BPL)

__global__ void __launch_bounds__(256, 3) gemm_pass(int pi)
{
    extern __shared__ char smem[];
    const uint32_t smb = smem_u32(smem);
    const PassArgs& a = g_pass[pi];
    const int tid = threadIdx.x, lane = tid & 31, w = tid >> 5;
    const int warpM = w & 3, warpN = w >> 2;
    const int rowbase = blockIdx.y * 128;
    const int mode = a.mode;
    const int segFixed = (mode == 3) ? blockIdx.x : -1;
    const int nb = (mode == 3) ? 0 : blockIdx.x * NT;

    const int nseg = a.nseg;
    int totalc = 0;
    if (mode == 3) totalc = a.K[segFixed] / 32;
    else {
        #pragma unroll
        for (int s = 0; s < 4; s++) if (s < nseg) totalc += a.K[s] / 32;
    }

    // ---- staging state (loop-carried) ----
    const int rA = tid >> 2, jb = tid & 3;
    const uint32_t dA0 = swz(rA, jb);
    int sSeg = (mode == 3) ? segFixed : 0;
    int remain = 0;
    const bf *pAh = nullptr, *pAl = nullptr, *pBh = nullptr, *pBl = nullptr;
    size_t strideA = 0;
    uint32_t sbW = smb;

    auto segInit = [&](int s) {
        const int Ks = a.K[s];
        size_t aoff = (size_t)(rowbase + rA) * Ks + jb * 8;
        size_t boff = (size_t)(nb + rA) * Ks + jb * 8;
        pAh = a.Ah[s] + aoff; pAl = a.Al[s] + aoff;
        pBh = a.Bh[s] + boff; pBl = a.Bl[s] + boff;
        strideA = (size_t)64 * Ks;
        remain = Ks / 32;
    };
    segInit(sSeg);

    auto stage = [&]() {
        if (remain == 0) { sSeg++; segInit(sSeg); }
        cpa16(sbW + dA0, pAh);
        cpa16(sbW + APL + dA0, pAl);
        cpa16(sbW + 4096 + dA0, pAh + strideA);
        cpa16(sbW + APL + 4096 + dA0, pAl + strideA);
        cpa16(sbW + 16384 + dA0, pBh);
        cpa16(sbW + 16384 + BPL + dA0, pBl);
        CP_COMMIT();
        pAh += 32; pAl += 32; pBh += 32; pBl += 32;
        remain--;
        sbW += STG;
        if (sbW == smb + 3u * STG) sbW = smb;
    };

    // ---- compute-side LDSM base offsets ----
    const int tq = lane >> 3, rq = lane & 7;
    const int mA = warpM * 32 + (tq & 1) * 8 + rq;
    const int kselA = tq >> 1;
    const int xa = (mA >> 1) & 3;
    const int nB = warpN * 32 + (tq >> 1) * 8 + rq;
    const int kselB = tq & 1;
    const int xb = (nB >> 1) & 3;
    const uint32_t offA0 = (uint32_t)((mA << 6) + ((kselA ^ xa) << 4));
    const uint32_t offB0 = (uint32_t)(16384 + (nB << 6) + ((kselB ^ xb) << 4));

    // ---- preload epilogue constants ----
    const int npBase = nb + warpN * 32 + (lane & 3) * 2;
    float eb[NW8][2], ea[NW8][2];
    if (mode == 0 || mode == 1) {
        #pragma unroll
        for (int j = 0; j < NW8; j++) {
            eb[j][0] = __ldg(a.bias + npBase + j * 8);
            eb[j][1] = __ldg(a.bias + npBase + j * 8 + 1);
        }
        if (mode == 1) {
            #pragma unroll
            for (int j = 0; j < NW8; j++) {
                ea[j][0] = __ldg(a.aux + npBase + j * 8);
                ea[j][1] = __ldg(a.aux + npBase + j * 8 + 1);
            }
        }
    }

    float acc[2][NW8][4];
    #pragma unroll
    for (int i = 0; i < 2; i++)
        #pragma unroll
        for (int j = 0; j < NW8; j++)
            #pragma unroll
            for (int cq = 0; cq < 4; cq++) acc[i][j][cq] = 0.0f;

    uint32_t sbR = smb;
    auto compute = [&]() {
        #pragma unroll
        for (int k16 = 0; k16 < 2; k16++) {
            const uint32_t oA = offA0 ^ (uint32_t)(k16 << 5);
            const uint32_t oB = offB0 ^ (uint32_t)(k16 << 5);
            uint32_t ah[2][4], al[2][4];
            #pragma unroll
            for (int mt = 0; mt < 2; mt++) {
                uint32_t ad = sbR + oA + (uint32_t)(mt * 1024);
                LDSM4(ah[mt], ad);
                LDSM4(al[mt], ad + APL);
            }
            #pragma unroll
            for (int ti = 0; ti < 2; ti++) {
                uint32_t bh[4], bl[4];
                uint32_t bd = sbR + oB + (uint32_t)(ti * 1024);
                LDSM4(bh, bd);
                LDSM4(bl, bd + BPL);
                #pragma unroll
                for (int mt = 0; mt < 2; mt++)
                    #pragma unroll
                    for (int jj = 0; jj < 2; jj++) {
                        int j = ti * 2 + jj;
                        MMA16816(acc[mt][j], ah[mt], bh[jj * 2], bh[jj * 2 + 1]);
                        MMA16816(acc[mt][j], al[mt], bh[jj * 2], bh[jj * 2 + 1]);
                        MMA16816(acc[mt][j], ah[mt], bl[jj * 2], bl[jj * 2 + 1]);
                    }
            }
        }
        sbR += STG;
        if (sbR == smb + 3u * STG) sbR = smb;
    };

    stage();
    if (totalc > 1) stage();

    int c = 0;
    for (; c < totalc - 2; c++) {          // steady state
        CP_WAIT1();
        __syncthreads();
        compute();
        stage();
    }
    for (; c < totalc; c++) {              // tail (≤2 chunks)
        CP_WAIT0();
        __syncthreads();
        compute();
    }

    // ---- epilogue ----
    #pragma unroll
    for (int mt = 0; mt < 2; mt++)
        #pragma unroll
        for (int j = 0; j < NW8; j++) {
            float* q = acc[mt][j];
            const int m0 = rowbase + warpM * 32 + mt * 16 + (lane >> 2);
            const int np = npBase + j * 8;
            #pragma unroll
            for (int half = 0; half < 2; half++) {
                const int m = m0 + half * 8;
                float v0 = q[half * 2], v1 = q[half * 2 + 1];
                if (mode == 0) {
                    float p0 = v0 + eb[j][0], p1 = v1 + eb[j][1];
                    float z0, s0, z1, s1;
                    act(p0, z0, s0); act(p1, z1, s1);
                    st_split(a.oh, a.ol, (size_t)m * Hd + np, z0, z1);
                } else if (mode == 1) {
                    float p0 = v0 + eb[j][0], p1 = v1 + eb[j][1];
                    float zt, s0, s1;
                    act(p0, zt, s0); act(p1, zt, s1);
                    st_split(a.oh, a.ol, (size_t)m * Hd + np, ea[j][0] * s0, ea[j][1] * s1);
                } else if (mode == 2) {
                    size_t o = (size_t)m * Hd + np;
                    uint32_t zh2 = *reinterpret_cast<const uint32_t*>(a.sh + o);
                    uint32_t zl2 = *reinterpret_cast<const uint32_t*>(a.sl + o);
                    __nv_bfloat162 zhh = *reinterpret_cast<__nv_bfloat162*>(&zh2);
                    __nv_bfloat162 zll = *reinterpret_cast<__nv_bfloat162*>(&zl2);
                    float z0 = __bfloat162float(zhh.x) + __bfloat162float(zll.x);
                    float z1 = __bfloat162float(zhh.y) + __bfloat162float(zll.y);
                    float s0 = -expm1f(-z0);     // sigmoid(p) = 1 - exp(-softplus(p))
                    float s1 = -expm1f(-z1);
                    st_split(a.oh, a.ol, o, s0 * v0, s1 * v1);
                } else {
                    float2 r; r.x = v0; r.y = v1;
                    *reinterpret_cast<float2*>(g_gpart[segFixed] + (size_t)m * Dd + np) = r;
                }
            }
        }
}

// ---------------------------------------------------------------------------
extern "C" void kernel_launch(void* const* d_in, const int* in_sizes, int n_in,
                              void* d_out, int out_size)
{
    const float* state = (const float*)d_in[0];
    const float* Wz0   = (const float*)d_in[1];
    const float* bz0   = (const float*)d_in[2];
    const float* Wz1   = (const float*)d_in[3];
    const float* Wz2   = (const float*)d_in[4];
    const float* Wz3   = (const float*)d_in[5];
    const float* WzL   = (const float*)d_in[6];
    const float* Wx0   = (const float*)d_in[7];
    const float* bx0   = (const float*)d_in[8];
    const float* Wx1   = (const float*)d_in[9];
    const float* bx1   = (const float*)d_in[10];
    const float* Wx2   = (const float*)d_in[11];
    const float* bx2   = (const float*)d_in[12];
    const float* WxL   = (const float*)d_in[13];
    float* out = (float*)d_out;

    const int smem_bytes = 3 * STG;     // 72 KB; 3 CTAs/SM = 216 KB
    cudaFuncSetAttribute(gemm_pass, cudaFuncAttributeMaxDynamicSharedMemorySize, smem_bytes);

    prep_all<<<512, 256>>>(Wz0, Wz1, Wz2, Wz3, Wx0, Wx1, Wx2, state,
                           bz0, bx0, bx1, bx2, WzL, WxL);
    prep_trans<<<288, 256>>>(Wz0, Wz1, Wz2, Wz3, Wx0, Wx1, Wx2);

    dim3 g(Hd / NT, Bsz / 128);         // (8, 512)
    for (int p = 0; p < 7; p++)
        gemm_pass<<<g, 256, smem_bytes>>>(p);
    gemm_pass<<<dim3(4, Bsz / 128), 256, smem_bytes>>>(7);
    grad_reduce<<<512, 256>>>(WxL, out);
}

// round 13
// speedup vs baseline: 1.5336x; 1.5336x over previous
#include <cuda_runtime.h>
#include <cuda_bf16.h>
#include <cstdint>

#define Bsz 65536
#define Hd 512
#define Dd 64
typedef __nv_bfloat16 bf;

// ---- static device scratch (no cudaMalloc allowed) ----
static __device__ __align__(16) bf g_Wz_h[3][Hd * Hd],  g_Wz_l[3][Hd * Hd];   // fwd [n][k]
static __device__ __align__(16) bf g_WzT_h[3][Hd * Hd], g_WzT_l[3][Hd * Hd];  // bwd [n][k]
static __device__ __align__(16) bf g_Wz0_h[Hd * Dd],    g_Wz0_l[Hd * Dd];
static __device__ __align__(16) bf g_Wx_h[3][Hd * Dd],  g_Wx_l[3][Hd * Dd];
static __device__ __align__(16) bf g_GT_h[4][Dd * Hd],  g_GT_l[4][Dd * Hd];   // grad B [64][512]
static __device__ __align__(16) bf g_x_h[(size_t)Bsz * Dd],  g_x_l[(size_t)Bsz * Dd];
static __device__ __align__(16) bf g_z_h[3][(size_t)Bsz * Hd], g_z_l[3][(size_t)Bsz * Hd];
static __device__ __align__(16) bf g_d4_h[(size_t)Bsz * Hd], g_d4_l[(size_t)Bsz * Hd];
static __device__ float g_gpart[4][(size_t)Bsz * Dd];   // grad partials per segment

struct PassArgs {
    const bf *Ah[4], *Al[4], *Bh[4], *Bl[4];
    int K[4]; int nseg; int mode;       // 0 fwd, 1 last, 2 bwd, 3 grad
    const float *bias, *aux;
    const bf *sh, *sl;                  // z planes for sigmoid recompute (mode 2)
    bf *oh, *ol;                        // bf16 hi/lo output planes
};
static __device__ PassArgs g_pass[8];

// ---- PTX helpers ----
__device__ __forceinline__ uint32_t smem_u32(const void* p) {
    uint32_t a;
    asm("{ .reg .u64 t; cvta.to.shared.u64 t, %1; cvt.u32.u64 %0, t; }" : "=r"(a) : "l"(p));
    return a;
}
__device__ __forceinline__ void cpa16(uint32_t dst, const void* src) {
    asm volatile("cp.async.cg.shared.global [%0], [%1], 16;" :: "r"(dst), "l"(src));
}
#define CP_COMMIT() asm volatile("cp.async.commit_group;" ::: "memory")
#define CP_WAIT1()  asm volatile("cp.async.wait_group 1;" ::: "memory")
#define CP_WAIT0()  asm volatile("cp.async.wait_group 0;" ::: "memory")
#define LDSM4(R, addr) \
    asm volatile("ldmatrix.sync.aligned.m8n8.x4.shared.b16 {%0,%1,%2,%3}, [%4];" \
        : "=r"((R)[0]), "=r"((R)[1]), "=r"((R)[2]), "=r"((R)[3]) : "r"(addr))
#define MMA16816(c, A, b0, b1) \
    asm volatile("mma.sync.aligned.m16n8k16.row.col.f32.bf16.bf16.f32 " \
        "{%0,%1,%2,%3}, {%4,%5,%6,%7}, {%8,%9}, {%0,%1,%2,%3};" \
        : "+f"((c)[0]), "+f"((c)[1]), "+f"((c)[2]), "+f"((c)[3]) \
        : "r"((A)[0]), "r"((A)[1]), "r"((A)[2]), "r"((A)[3]), "r"(b0), "r"(b1))

__device__ __forceinline__ void act(float p, float& z, float& s) {
    float e = __expf(-fabsf(p));
    float r = 1.0f / (1.0f + e);
    z = fmaxf(p, 0.0f) + log1pf(e);
    s = (p >= 0.0f) ? r : e * r;
}
__device__ __forceinline__ void bsplit(float v, bf& h, bf& l) {
    h = __float2bfloat16(v);
    l = __float2bfloat16(v - __bfloat162float(h));
}
__device__ __forceinline__ uint32_t pk2(bf a, bf b) {
    __nv_bfloat162 t(a, b);
    return *reinterpret_cast<uint32_t*>(&t);
}
__device__ __forceinline__ void st_split(bf* ph, bf* pl, size_t off, float v0, float v1) {
    bf h0, l0, h1, l1;
    bsplit(v0, h0, l0); bsplit(v1, h1, l1);
    *reinterpret_cast<uint32_t*>(ph + off) = pk2(h0, h1);
    *reinterpret_cast<uint32_t*>(pl + off) = pk2(l0, l1);
}
__device__ __forceinline__ uint32_t swz(int r, int jb) {
    return (uint32_t)((r << 6) + ((jb ^ ((r >> 1) & 3)) << 4));
}

// ---- prep 1: coalesced splits (fwd planes, x) + pass args ----
__global__ void prep_all(const float* __restrict__ Wz0, const float* __restrict__ Wz1,
                         const float* __restrict__ Wz2, const float* __restrict__ Wz3,
                         const float* __restrict__ Wx0, const float* __restrict__ Wx1,
                         const float* __restrict__ Wx2, const float* __restrict__ state,
                         const float* bz0, const float* bx0, const float* bx1,
                         const float* bx2, const float* WzL, const float* WxL)
{
    const float* Wz[3] = { Wz1, Wz2, Wz3 };
    const float* Wx[3] = { Wx0, Wx1, Wx2 };
    for (int i = blockIdx.x * blockDim.x + threadIdx.x; i < Hd * Hd;
         i += gridDim.x * blockDim.x) {
        #pragma unroll
        for (int l = 0; l < 3; l++) {
            bf h, lo; bsplit(Wz[l][i], h, lo);
            g_Wz_h[l][i] = h; g_Wz_l[l][i] = lo;
        }
        if (i < Hd * Dd) {
            bf h, lo; bsplit(Wz0[i], h, lo);
            g_Wz0_h[i] = h; g_Wz0_l[i] = lo;
            #pragma unroll
            for (int l = 0; l < 3; l++) {
                bsplit(Wx[l][i], h, lo);
                g_Wx_h[l][i] = h; g_Wx_l[l][i] = lo;
            }
        }
    }
    for (size_t i = blockIdx.x * blockDim.x + threadIdx.x; i < (size_t)Bsz * Dd;
         i += (size_t)gridDim.x * blockDim.x) {
        bf h, l; bsplit(state[i] - 1.0f, h, l);
        g_x_h[i] = h; g_x_l[i] = l;
    }
    if (blockIdx.x == 0 && threadIdx.x == 0) {
        auto set = [] (int p, int nseg, int mode, const float* bias, const float* aux,
                       const bf* sh, const bf* sl, bf* oh, bf* ol) {
            PassArgs& a = g_pass[p];
            a.nseg = nseg; a.mode = mode; a.bias = bias; a.aux = aux;
            a.sh = sh; a.sl = sl; a.oh = oh; a.ol = ol;
        };
        auto seg = [] (int p, int s, const bf* Ah, const bf* Al, const bf* Bh, const bf* Bl, int K) {
            PassArgs& a = g_pass[p];
            a.Ah[s] = Ah; a.Al[s] = Al; a.Bh[s] = Bh; a.Bl[s] = Bl; a.K[s] = K;
        };
        set(0, 1, 0, bz0, 0, 0, 0, g_z_h[0], g_z_l[0]);
        seg(0, 0, g_x_h, g_x_l, g_Wz0_h, g_Wz0_l, Dd);
        set(1, 2, 0, bx0, 0, 0, 0, g_z_h[1], g_z_l[1]);
        seg(1, 0, g_z_h[0], g_z_l[0], g_Wz_h[0], g_Wz_l[0], Hd);
        seg(1, 1, g_x_h, g_x_l, g_Wx_h[0], g_Wx_l[0], Dd);
        set(2, 2, 0, bx1, 0, 0, 0, g_z_h[2], g_z_l[2]);
        seg(2, 0, g_z_h[1], g_z_l[1], g_Wz_h[1], g_Wz_l[1], Hd);
        seg(2, 1, g_x_h, g_x_l, g_Wx_h[1], g_Wx_l[1], Dd);
        set(3, 2, 1, bx2, WzL, 0, 0, g_d4_h, g_d4_l);
        seg(3, 0, g_z_h[2], g_z_l[2], g_Wz_h[2], g_Wz_l[2], Hd);
        seg(3, 1, g_x_h, g_x_l, g_Wx_h[2], g_Wx_l[2], Dd);
        set(4, 1, 2, 0, 0, g_z_h[2], g_z_l[2], g_z_h[2], g_z_l[2]);
        seg(4, 0, g_d4_h, g_d4_l, g_WzT_h[2], g_WzT_l[2], Hd);
        set(5, 1, 2, 0, 0, g_z_h[1], g_z_l[1], g_z_h[1], g_z_l[1]);
        seg(5, 0, g_z_h[2], g_z_l[2], g_WzT_h[1], g_WzT_l[1], Hd);
        set(6, 1, 2, 0, 0, g_z_h[0], g_z_l[0], g_z_h[0], g_z_l[0]);
        seg(6, 0, g_z_h[1], g_z_l[1], g_WzT_h[0], g_WzT_l[0], Hd);
        set(7, 4, 3, 0, WxL, 0, 0, 0, 0);
        seg(7, 0, g_z_h[0], g_z_l[0], g_GT_h[0], g_GT_l[0], Hd);
        seg(7, 1, g_z_h[1], g_z_l[1], g_GT_h[1], g_GT_l[1], Hd);
        seg(7, 2, g_z_h[2], g_z_l[2], g_GT_h[2], g_GT_l[2], Hd);
        seg(7, 3, g_d4_h, g_d4_l, g_GT_h[3], g_GT_l[3], Hd);
    }
}

// ---- prep 2: coalesced 32x32 smem-tile transposes ----
__global__ void prep_trans(const float* __restrict__ Wz0, const float* __restrict__ Wz1,
                           const float* __restrict__ Wz2, const float* __restrict__ Wz3,
                           const float* __restrict__ Wx0, const float* __restrict__ Wx1,
                           const float* __restrict__ Wx2)
{
    __shared__ float tile[32][33];
    const int tid = threadIdx.x;
    const int c = tid & 31, r0 = tid >> 5;
    const int b = blockIdx.x;

    if (b < 256) {
        const float* src[3] = { Wz1, Wz2, Wz3 };
        bf* dh[3] = { g_WzT_h[0], g_WzT_h[1], g_WzT_h[2] };
        bf* dl[3] = { g_WzT_l[0], g_WzT_l[1], g_WzT_l[2] };
        const int tr = (b >> 4) * 32, tc = (b & 15) * 32;
        for (int l = 0; l < 3; l++) {
            __syncthreads();
            #pragma unroll
            for (int it = 0; it < 4; it++) {
                int r = r0 + it * 8;
                tile[r][c] = src[l][(tr + r) * Hd + tc + c];
            }
            __syncthreads();
            #pragma unroll
            for (int it = 0; it < 4; it++) {
                int r = r0 + it * 8;
                bf h, lo; bsplit(tile[c][r], h, lo);
                dh[l][(tc + r) * Hd + tr + c] = h;
                dl[l][(tc + r) * Hd + tr + c] = lo;
            }
        }
    } else {
        const float* src[4] = { Wz0, Wx0, Wx1, Wx2 };
        const int idx = b - 256;
        const int tr = (idx >> 1) * 32, tc = (idx & 1) * 32;
        for (int l = 0; l < 4; l++) {
            __syncthreads();
            #pragma unroll
            for (int it = 0; it < 4; it++) {
                int r = r0 + it * 8;
                tile[r][c] = src[l][(tr + r) * Dd + tc + c];
            }
            __syncthreads();
            #pragma unroll
            for (int it = 0; it < 4; it++) {
                int r = r0 + it * 8;
                bf h, lo; bsplit(tile[c][r], h, lo);
                g_GT_h[l][(tc + r) * Hd + tr + c] = h;
                g_GT_l[l][(tc + r) * Hd + tr + c] = lo;
            }
        }
    }
}

__global__ void grad_reduce(const float* __restrict__ WxL, float* __restrict__ out)
{
    for (size_t i = blockIdx.x * blockDim.x + threadIdx.x; i < (size_t)Bsz * Dd;
         i += (size_t)gridDim.x * blockDim.x) {
        out[i] = g_gpart[0][i] + g_gpart[1][i] + g_gpart[2][i] + g_gpart[3][i]
               + __ldg(WxL + (i & 63));
    }
}

// ---------------------------------------------------------------------------
// GEMM pass: CTA 128m x 64n, 256 thr, bf16 3-product mma.sync,
// 3-stage cp.async pipeline, 3 CTAs/SM (R9 structure — best known).
// ---------------------------------------------------------------------------
#define NT 64
#define NW8 4
#define APL 8192            // A plane bytes (128 x 32 x bf16)
#define BPL 4096            // B plane bytes (64 x 32 x bf16)
#define STG (16384 + 2 * BPL)

__global__ void __launch_bounds__(256, 3) gemm_pass(int pi)
{
    extern __shared__ char smem[];
    const uint32_t smb = smem_u32(smem);
    const PassArgs& a = g_pass[pi];
    const int tid = threadIdx.x, lane = tid & 31, w = tid >> 5;
    const int warpM = w & 3, warpN = w >> 2;
    const int rowbase = blockIdx.y * 128;
    const int mode = a.mode;
    const int segFixed = (mode == 3) ? blockIdx.x : -1;
    const int nb = (mode == 3) ? 0 : blockIdx.x * NT;

    const int nseg = a.nseg;
    int totalc = 0;
    if (mode == 3) totalc = a.K[segFixed] / 32;
    else {
        #pragma unroll
        for (int s = 0; s < 4; s++) if (s < nseg) totalc += a.K[s] / 32;
    }

    // ---- staging state (loop-carried) ----
    const int rA = tid >> 2, jb = tid & 3;
    const uint32_t dA0 = swz(rA, jb);
    int sSeg = (mode == 3) ? segFixed : 0;
    int remain = 0;
    const bf *pAh = nullptr, *pAl = nullptr, *pBh = nullptr, *pBl = nullptr;
    size_t strideA = 0;
    uint32_t sbW = smb;

    auto segInit = [&](int s) {
        const int Ks = a.K[s];
        size_t aoff = (size_t)(rowbase + rA) * Ks + jb * 8;
        size_t boff = (size_t)(nb + rA) * Ks + jb * 8;
        pAh = a.Ah[s] + aoff; pAl = a.Al[s] + aoff;
        pBh = a.Bh[s] + boff; pBl = a.Bl[s] + boff;
        strideA = (size_t)64 * Ks;
        remain = Ks / 32;
    };
    segInit(sSeg);

    auto stage = [&]() {
        if (remain == 0) { sSeg++; segInit(sSeg); }
        cpa16(sbW + dA0, pAh);
        cpa16(sbW + APL + dA0, pAl);
        cpa16(sbW + 4096 + dA0, pAh + strideA);
        cpa16(sbW + APL + 4096 + dA0, pAl + strideA);
        cpa16(sbW + 16384 + dA0, pBh);
        cpa16(sbW + 16384 + BPL + dA0, pBl);
        CP_COMMIT();
        pAh += 32; pAl += 32; pBh += 32; pBl += 32;
        remain--;
        sbW += STG;
        if (sbW == smb + 3u * STG) sbW = smb;
    };

    // ---- compute-side LDSM base offsets ----
    const int tq = lane >> 3, rq = lane & 7;
    const int mA = warpM * 32 + (tq & 1) * 8 + rq;
    const int kselA = tq >> 1;
    const int xa = (mA >> 1) & 3;
    const int nB = warpN * 32 + (tq >> 1) * 8 + rq;
    const int kselB = tq & 1;
    const int xb = (nB >> 1) & 3;
    const uint32_t offA0 = (uint32_t)((mA << 6) + ((kselA ^ xa) << 4));
    const uint32_t offB0 = (uint32_t)(16384 + (nB << 6) + ((kselB ^ xb) << 4));

    // ---- preload epilogue constants ----
    const int npBase = nb + warpN * 32 + (lane & 3) * 2;
    float eb[NW8][2], ea[NW8][2];
    if (mode == 0 || mode == 1) {
        #pragma unroll
        for (int j = 0; j < NW8; j++) {
            eb[j][0] = __ldg(a.bias + npBase + j * 8);
            eb[j][1] = __ldg(a.bias + npBase + j * 8 + 1);
        }
        if (mode == 1) {
            #pragma unroll
            for (int j = 0; j < NW8; j++) {
                ea[j][0] = __ldg(a.aux + npBase + j * 8);
                ea[j][1] = __ldg(a.aux + npBase + j * 8 + 1);
            }
        }
    }

    float acc[2][NW8][4];
    #pragma unroll
    for (int i = 0; i < 2; i++)
        #pragma unroll
        for (int j = 0; j < NW8; j++)
            #pragma unroll
            for (int cq = 0; cq < 4; cq++) acc[i][j][cq] = 0.0f;

    uint32_t sbR = smb;
    auto compute = [&]() {
        #pragma unroll
        for (int k16 = 0; k16 < 2; k16++) {
            const uint32_t oA = offA0 ^ (uint32_t)(k16 << 5);
            const uint32_t oB = offB0 ^ (uint32_t)(k16 << 5);
            uint32_t ah[2][4], al[2][4];
            #pragma unroll
            for (int mt = 0; mt < 2; mt++) {
                uint32_t ad = sbR + oA + (uint32_t)(mt * 1024);
                LDSM4(ah[mt], ad);
                LDSM4(al[mt], ad + APL);
            }
            #pragma unroll
            for (int ti = 0; ti < 2; ti++) {
                uint32_t bh[4], bl[4];
                uint32_t bd = sbR + oB + (uint32_t)(ti * 1024);
                LDSM4(bh, bd);
                LDSM4(bl, bd + BPL);
                #pragma unroll
                for (int mt = 0; mt < 2; mt++)
                    #pragma unroll
                    for (int jj = 0; jj < 2; jj++) {
                        int j = ti * 2 + jj;
                        MMA16816(acc[mt][j], ah[mt], bh[jj * 2], bh[jj * 2 + 1]);
                        MMA16816(acc[mt][j], al[mt], bh[jj * 2], bh[jj * 2 + 1]);
                        MMA16816(acc[mt][j], ah[mt], bl[jj * 2], bl[jj * 2 + 1]);
                    }
            }
        }
        sbR += STG;
        if (sbR == smb + 3u * STG) sbR = smb;
    };

    stage();
    if (totalc > 1) stage();

    int c = 0;
    for (; c < totalc - 2; c++) {          // steady state
        CP_WAIT1();
        __syncthreads();
        compute();
        stage();
    }
    for (; c < totalc; c++) {              // tail (≤2 chunks)
        CP_WAIT0();
        __syncthreads();
        compute();
    }

    // ---- epilogue ----
    #pragma unroll
    for (int mt = 0; mt < 2; mt++)
        #pragma unroll
        for (int j = 0; j < NW8; j++) {
            float* q = acc[mt][j];
            const int m0 = rowbase + warpM * 32 + mt * 16 + (lane >> 2);
            const int np = npBase + j * 8;
            #pragma unroll
            for (int half = 0; half < 2; half++) {
                const int m = m0 + half * 8;
                float v0 = q[half * 2], v1 = q[half * 2 + 1];
                if (mode == 0) {
                    float p0 = v0 + eb[j][0], p1 = v1 + eb[j][1];
                    float z0, s0, z1, s1;
                    act(p0, z0, s0); act(p1, z1, s1);
                    st_split(a.oh, a.ol, (size_t)m * Hd + np, z0, z1);
                } else if (mode == 1) {
                    float p0 = v0 + eb[j][0], p1 = v1 + eb[j][1];
                    float zt, s0, s1;
                    act(p0, zt, s0); act(p1, zt, s1);
                    st_split(a.oh, a.ol, (size_t)m * Hd + np, ea[j][0] * s0, ea[j][1] * s1);
                } else if (mode == 2) {
                    size_t o = (size_t)m * Hd + np;
                    uint32_t zh2 = *reinterpret_cast<const uint32_t*>(a.sh + o);
                    uint32_t zl2 = *reinterpret_cast<const uint32_t*>(a.sl + o);
                    __nv_bfloat162 zhh = *reinterpret_cast<__nv_bfloat162*>(&zh2);
                    __nv_bfloat162 zll = *reinterpret_cast<__nv_bfloat162*>(&zl2);
                    float z0 = __bfloat162float(zhh.x) + __bfloat162float(zll.x);
                    float z1 = __bfloat162float(zhh.y) + __bfloat162float(zll.y);
                    float s0 = -expm1f(-z0);     // sigmoid(p) = 1 - exp(-softplus(p))
                    float s1 = -expm1f(-z1);
                    st_split(a.oh, a.ol, o, s0 * v0, s1 * v1);
                } else {
                    float2 r; r.x = v0; r.y = v1;
                    *reinterpret_cast<float2*>(g_gpart[segFixed] + (size_t)m * Dd + np) = r;
                }
            }
        }
}

// ---------------------------------------------------------------------------
extern "C" void kernel_launch(void* const* d_in, const int* in_sizes, int n_in,
                              void* d_out, int out_size)
{
    const float* state = (const float*)d_in[0];
    const float* Wz0   = (const float*)d_in[1];
    const float* bz0   = (const float*)d_in[2];
    const float* Wz1   = (const float*)d_in[3];
    const float* Wz2   = (const float*)d_in[4];
    const float* Wz3   = (const float*)d_in[5];
    const float* WzL   = (const float*)d_in[6];
    const float* Wx0   = (const float*)d_in[7];
    const float* bx0   = (const float*)d_in[8];
    const float* Wx1   = (const float*)d_in[9];
    const float* bx1   = (const float*)d_in[10];
    const float* Wx2   = (const float*)d_in[11];
    const float* bx2   = (const float*)d_in[12];
    const float* WxL   = (const float*)d_in[13];
    float* out = (float*)d_out;

    const int smem_bytes = 3 * STG;     // 72 KB; 3 CTAs/SM = 216 KB
    cudaFuncSetAttribute(gemm_pass, cudaFuncAttributeMaxDynamicSharedMemorySize, smem_bytes);

    prep_all<<<512, 256>>>(Wz0, Wz1, Wz2, Wz3, Wx0, Wx1, Wx2, state,
                           bz0, bx0, bx1, bx2, WzL, WxL);
    prep_trans<<<288, 256>>>(Wz0, Wz1, Wz2, Wz3, Wx0, Wx1, Wx2);

    dim3 g(Hd / NT, Bsz / 128);         // (8, 512)
    for (int p = 0; p < 7; p++)
        gemm_pass<<<g, 256, smem_bytes>>>(p);
    gemm_pass<<<dim3(4, Bsz / 128), 256, smem_bytes>>>(7);
    grad_reduce<<<512, 256>>>(WxL, out);
}